// round 15
// baseline (speedup 1.0000x reference)
#include <cuda_runtime.h>
#include <cuda_bf16.h>
#include <cstdint>

#define F 128
#define MAXN 100000
#define MAXNP 100096   // padded to multiple of 128 (GEMM tile)
#define MAXE 1600000
#define SCAN_B 1024
#define MAXBLK ((MAXN + SCAN_B - 1) / SCAN_B)   // 98

// Scratch (allocation-free: __device__ globals)
__device__ __align__(16) float    g_bufA[(size_t)MAXNP * F];       // gemm out (both layers)
__device__ __align__(16) uint32_t g_Xhi[(size_t)MAXNP * (F / 2)];  // bf16 pairs
__device__ __align__(16) uint32_t g_Xlo[(size_t)MAXNP * (F / 2)];
__device__ __align__(4) unsigned short g_W1hi[F * F];  // [n][k] transposed
__device__ __align__(4) unsigned short g_W1lo[F * F];
__device__ __align__(4) unsigned short g_W2hi[F * F];
__device__ __align__(4) unsigned short g_W2lo[F * F];
__device__ int   g_cntIn[MAXN];
__device__ int   g_cntOut[MAXN];
__device__ int   g_excl[MAXN];
__device__ int   g_bsum[MAXBLK];
__device__ int   g_off[MAXN];
__device__ int   g_cursor[MAXN];
__device__ int   g_eidx[MAXE];
__device__ float g_dinvOut[MAXNP];   // padded rows stay 0 (never written)
__device__ float g_dinvIn[MAXNP];

__device__ __forceinline__ void split_bf16(float v, unsigned short& h, unsigned short& l) {
    __nv_bfloat16 hb = __float2bfloat16(v);
    __nv_bfloat16 lb = __float2bfloat16(v - __bfloat162float(hb));
    h = __bfloat16_as_ushort(hb);
    l = __bfloat16_as_ushort(lb);
}

// ---------------------------------------------------------------------------
// Fused setup: zero both histograms AND split both weight matrices.
__global__ void setup_kernel(const float* __restrict__ W1,
                             const float* __restrict__ W2, int n) {
    int i = blockIdx.x * blockDim.x + threadIdx.x;
    if (i < n) { g_cntIn[i] = 0; g_cntOut[i] = 0; }
    if (i < 2 * F * F) {
        int which = i >> 14;
        int t = i & 16383;
        int k = t >> 7, nn = t & 127;
        unsigned short h, l;
        if (which == 0) {
            split_bf16(W1[t], h, l);
            g_W1hi[nn * F + k] = h; g_W1lo[nn * F + k] = l;
        } else {
            split_bf16(W2[t], h, l);
            g_W2hi[nn * F + k] = h; g_W2lo[nn * F + k] = l;
        }
    }
}

__global__ void hist_kernel(const int2* __restrict__ src2,
                            const int2* __restrict__ dst2, int nE2, int odd,
                            const int* __restrict__ src,
                            const int* __restrict__ dst) {
    int i = blockIdx.x * blockDim.x + threadIdx.x;
    if (i < nE2) {
        int2 s = src2[i];
        int2 d = dst2[i];
        atomicAdd(&g_cntOut[s.x], 1);
        atomicAdd(&g_cntOut[s.y], 1);
        atomicAdd(&g_cntIn[d.x], 1);
        atomicAdd(&g_cntIn[d.y], 1);
    } else if (i == nE2 && odd) {
        atomicAdd(&g_cntOut[src[2 * nE2]], 1);
        atomicAdd(&g_cntIn[dst[2 * nE2]], 1);
    }
}

// Shuffle-based block scan (2 barriers) + fused dinv computation
__global__ void scan_block_kernel(int n) {
    __shared__ int wsum[32];
    int tid = threadIdx.x, lane = tid & 31, w = tid >> 5;
    int i = blockIdx.x * SCAN_B + tid;
    int v = (i < n) ? g_cntIn[i] : 0;
    int x = v;
#pragma unroll
    for (int o = 1; o < 32; o <<= 1) {
        int t = __shfl_up_sync(0xffffffffu, x, o);
        if (lane >= o) x += t;
    }
    if (lane == 31) wsum[w] = x;
    // fused dinv (independent of scan; hides the barrier)
    if (i < n) {
        g_dinvIn[i]  = rsqrtf(fmaxf((float)v, 1.f));
        g_dinvOut[i] = rsqrtf(fmaxf((float)g_cntOut[i], 1.f));
    }
    __syncthreads();
    if (w == 0) {
        int s = wsum[lane];
#pragma unroll
        for (int o = 1; o < 32; o <<= 1) {
            int t = __shfl_up_sync(0xffffffffu, s, o);
            if (lane >= o) s += t;
        }
        wsum[lane] = s;
    }
    __syncthreads();
    int incl = x + ((w > 0) ? wsum[w - 1] : 0);
    if (i < n) g_excl[i] = incl - v;
    if (tid == SCAN_B - 1) g_bsum[blockIdx.x] = incl;
}

__global__ void scan_small_kernel(int nb) {
    __shared__ int wsum[4];
    int tid = threadIdx.x, lane = tid & 31, w = tid >> 5;
    int v = (tid < nb) ? g_bsum[tid] : 0;
    int x = v;
#pragma unroll
    for (int o = 1; o < 32; o <<= 1) {
        int t = __shfl_up_sync(0xffffffffu, x, o);
        if (lane >= o) x += t;
    }
    if (lane == 31) wsum[w] = x;
    __syncthreads();
    int base = 0;
#pragma unroll
    for (int q = 0; q < 4; q++) base += (q < w) ? wsum[q] : 0;
    if (tid < nb) g_bsum[tid] = base + x - v;
}

__global__ void offsets_kernel(int n) {
    int i = blockIdx.x * blockDim.x + threadIdx.x;
    if (i < n) {
        int o = g_excl[i] + g_bsum[i / SCAN_B];
        g_off[i] = o;
        g_cursor[i] = o;
    }
}

__global__ void fill_kernel(const int2* __restrict__ src2,
                            const int2* __restrict__ dst2, int nE2, int odd,
                            const int* __restrict__ src,
                            const int* __restrict__ dst) {
    int i = blockIdx.x * blockDim.x + threadIdx.x;
    if (i < nE2) {
        int2 s = src2[i];
        int2 d = dst2[i];
        int p0 = atomicAdd(&g_cursor[d.x], 1);
        g_eidx[p0] = s.x;
        int p1 = atomicAdd(&g_cursor[d.y], 1);
        g_eidx[p1] = s.y;
    } else if (i == nE2 && odd) {
        int p = atomicAdd(&g_cursor[dst[2 * nE2]], 1);
        g_eidx[p] = src[2 * nE2];
    }
}

// features -> split bf16 hi/lo (no scaling; dinvOut applied in gemm1 epilogue)
__global__ void prep_kernel(const float* __restrict__ feat, int nN) {
    int i = blockIdx.x * blockDim.x + threadIdx.x;   // one float4 each
    if (i >= nN * 32) return;
    int row = i >> 5, c4 = i & 31;
    float4 v = ((const float4*)feat)[i];
    unsigned short h0, l0, h1, l1, h2, l2, h3, l3;
    split_bf16(v.x, h0, l0); split_bf16(v.y, h1, l1);
    split_bf16(v.z, h2, l2); split_bf16(v.w, h3, l3);
    size_t w = (size_t)row * 64 + c4 * 2;
    g_Xhi[w]     = (uint32_t)h0 | ((uint32_t)h1 << 16);
    g_Xhi[w + 1] = (uint32_t)h2 | ((uint32_t)h3 << 16);
    g_Xlo[w]     = (uint32_t)l0 | ((uint32_t)l1 << 16);
    g_Xlo[w + 1] = (uint32_t)l2 | ((uint32_t)l3 << 16);
}

// ---------------------------------------------------------------------------
// bf16x3 tensor-core GEMM with ldmatrix; optional row-scale (dinvOut) on store.
#define XPITCH 40

__device__ __forceinline__ void mma_bf16(float* d, const uint32_t* a,
                                         uint32_t b0, uint32_t b1) {
    asm volatile(
        "mma.sync.aligned.m16n8k16.row.col.f32.bf16.bf16.f32 "
        "{%0,%1,%2,%3}, {%4,%5,%6,%7}, {%8,%9}, {%0,%1,%2,%3};"
        : "+f"(d[0]), "+f"(d[1]), "+f"(d[2]), "+f"(d[3])
        : "r"(a[0]), "r"(a[1]), "r"(a[2]), "r"(a[3]), "r"(b0), "r"(b1));
}

__device__ __forceinline__ void ldsm_x4(uint32_t& r0, uint32_t& r1,
                                        uint32_t& r2, uint32_t& r3,
                                        const void* p) {
    uint32_t a = (uint32_t)__cvta_generic_to_shared(p);
    asm volatile("ldmatrix.sync.aligned.m8n8.x4.shared.b16 {%0,%1,%2,%3}, [%4];"
                 : "=r"(r0), "=r"(r1), "=r"(r2), "=r"(r3) : "r"(a));
}

__global__ __launch_bounds__(256, 2)
void gemm_mma_kernel(const unsigned short* __restrict__ Whi,
                     const unsigned short* __restrict__ Wlo, int nN,
                     int scaleOut) {
    __shared__ __align__(16) unsigned short sXhi[128][XPITCH];
    __shared__ __align__(16) unsigned short sXlo[128][XPITCH];
    __shared__ __align__(16) unsigned short sWhi[128][XPITCH];
    __shared__ __align__(16) unsigned short sWlo[128][XPITCH];

    const int tid  = threadIdx.x;
    const int wid  = tid >> 5;
    const int lane = tid & 31;
    const int g    = lane >> 2;
    const int tig  = lane & 3;
    const int row0 = blockIdx.x * 128;
    const int wm   = wid & 3;
    const int wn   = wid >> 2;
    const uint32_t* Wh32 = (const uint32_t*)Whi;
    const uint32_t* Wl32 = (const uint32_t*)Wlo;

    const int lrow = (lane & 7) + ((lane >> 3) & 1) * 8;
    const int lcol = (lane >> 4) * 8;

    float acc[2][8][4];
#pragma unroll
    for (int mt = 0; mt < 2; mt++)
#pragma unroll
        for (int nt = 0; nt < 8; nt++)
#pragma unroll
            for (int q = 0; q < 4; q++) acc[mt][nt][q] = 0.f;

    for (int kc = 0; kc < 4; kc++) {
#pragma unroll
        for (int p = 0; p < 8; p++) {
            int idx = p * 256 + tid;
            int r   = idx >> 4;
            int pp  = idx & 15;
            int grow = row0 + r;
            uint32_t hw = 0, lw = 0;
            if (grow < nN) {
                size_t widx = (size_t)grow * 64 + kc * 16 + pp;
                hw = g_Xhi[widx];
                lw = g_Xlo[widx];
            }
            *(uint32_t*)&sXhi[r][2 * pp] = hw;
            *(uint32_t*)&sXlo[r][2 * pp] = lw;
        }
#pragma unroll
        for (int p = 0; p < 8; p++) {
            int idx = p * 256 + tid;
            int n   = idx >> 4;
            int pp  = idx & 15;
            int widx = n * 64 + kc * 16 + pp;
            *(uint32_t*)&sWhi[n][2 * pp] = Wh32[widx];
            *(uint32_t*)&sWlo[n][2 * pp] = Wl32[widx];
        }
        __syncthreads();

#pragma unroll
        for (int ks = 0; ks < 2; ks++) {
            int kb = ks * 16;
            uint32_t ah[2][4], al[2][4];
#pragma unroll
            for (int mt = 0; mt < 2; mt++) {
                int rb = wm * 32 + mt * 16;
                ldsm_x4(ah[mt][0], ah[mt][1], ah[mt][2], ah[mt][3],
                        &sXhi[rb + lrow][kb + lcol]);
                ldsm_x4(al[mt][0], al[mt][1], al[mt][2], al[mt][3],
                        &sXlo[rb + lrow][kb + lcol]);
            }
#pragma unroll
            for (int ntp = 0; ntp < 4; ntp++) {
                int n0 = wn * 64 + ntp * 16;
                uint32_t bh[4], bl[4];
                ldsm_x4(bh[0], bh[1], bh[2], bh[3], &sWhi[n0 + lrow][kb + lcol]);
                ldsm_x4(bl[0], bl[1], bl[2], bl[3], &sWlo[n0 + lrow][kb + lcol]);
#pragma unroll
                for (int sub = 0; sub < 2; sub++) {
                    int nt = 2 * ntp + sub;
#pragma unroll
                    for (int mt = 0; mt < 2; mt++) {
                        mma_bf16(acc[mt][nt], ah[mt], bh[sub], bh[2 + sub]);
                        mma_bf16(acc[mt][nt], ah[mt], bl[sub], bl[2 + sub]);
                        mma_bf16(acc[mt][nt], al[mt], bh[sub], bh[2 + sub]);
                    }
                }
            }
        }
        __syncthreads();
    }

#pragma unroll
    for (int mt = 0; mt < 2; mt++) {
        int r1 = row0 + wm * 32 + mt * 16 + g;
        float sa = 1.f, sb = 1.f;
        if (scaleOut) {
            sa = g_dinvOut[r1];       // padded rows read deterministic 0
            sb = g_dinvOut[r1 + 8];
        }
#pragma unroll
        for (int nt = 0; nt < 8; nt++) {
            int col = wn * 64 + nt * 8 + 2 * tig;
            *(float2*)(g_bufA + (size_t)r1 * F + col) =
                make_float2(acc[mt][nt][0] * sa, acc[mt][nt][1] * sa);
            *(float2*)(g_bufA + (size_t)(r1 + 8) * F + col) =
                make_float2(acc[mt][nt][2] * sb, acc[mt][nt][3] * sb);
        }
    }
}

// ---------------------------------------------------------------------------
// Gather-1: aggregate over bufA (unroll 8) + layer-2 transform + split -> Xhi/Xlo
__global__ void gather1_kernel(const float* __restrict__ b1, int nN) {
    int node = blockIdx.x * (blockDim.x >> 5) + (threadIdx.x >> 5);
    int lane = threadIdx.x & 31;
    if (node >= nN) return;
    int b = g_off[node];
    int e = b + g_cntIn[node];
    float4 acc = make_float4(0.f, 0.f, 0.f, 0.f);
    int j = b;
    int e8 = b + ((e - b) & ~7);
    for (; j < e8; j += 8) {
        float4 v[8];
#pragma unroll
        for (int q = 0; q < 8; q++) {
            int s = g_eidx[j + q];
            v[q] = ((const float4*)(g_bufA + (size_t)s * F))[lane];
        }
#pragma unroll
        for (int q = 0; q < 8; q++) {
            acc.x += v[q].x; acc.y += v[q].y; acc.z += v[q].z; acc.w += v[q].w;
        }
    }
    for (; j < e; j++) {
        int s = g_eidx[j];
        float4 v = ((const float4*)(g_bufA + (size_t)s * F))[lane];
        acc.x += v.x; acc.y += v.y; acc.z += v.z; acc.w += v.w;
    }
    float db = g_dinvIn[node];
    float da = g_dinvOut[node];
    float4 bb = ((const float4*)b1)[lane];
    float x0 = fmaxf(fmaf(acc.x, db, bb.x), 0.f) * da;
    float x1 = fmaxf(fmaf(acc.y, db, bb.y), 0.f) * da;
    float x2 = fmaxf(fmaf(acc.z, db, bb.z), 0.f) * da;
    float x3 = fmaxf(fmaf(acc.w, db, bb.w), 0.f) * da;
    unsigned short h0, l0, h1, l1, h2, l2, h3, l3;
    split_bf16(x0, h0, l0); split_bf16(x1, h1, l1);
    split_bf16(x2, h2, l2); split_bf16(x3, h3, l3);
    size_t w = (size_t)node * 64 + lane * 2;
    g_Xhi[w]     = (uint32_t)h0 | ((uint32_t)h1 << 16);
    g_Xhi[w + 1] = (uint32_t)h2 | ((uint32_t)h3 << 16);
    g_Xlo[w]     = (uint32_t)l0 | ((uint32_t)l1 << 16);
    g_Xlo[w + 1] = (uint32_t)l2 | ((uint32_t)l3 << 16);
}

// ---------------------------------------------------------------------------
// Gather-2 over bufA (unroll 8) + fused classifier
__global__ void gather2_cls_kernel(const float* __restrict__ b2,
                                   const float* __restrict__ Wc,
                                   const float* __restrict__ bc,
                                   float* __restrict__ out, int nN) {
    int node = blockIdx.x * (blockDim.x >> 5) + (threadIdx.x >> 5);
    int lane = threadIdx.x & 31;
    if (node >= nN) return;
    int b = g_off[node];
    int e = b + g_cntIn[node];
    float4 acc = make_float4(0.f, 0.f, 0.f, 0.f);
    int j = b;
    int e8 = b + ((e - b) & ~7);
    for (; j < e8; j += 8) {
        float4 v[8];
#pragma unroll
        for (int q = 0; q < 8; q++) {
            int s = g_eidx[j + q];
            v[q] = ((const float4*)(g_bufA + (size_t)s * F))[lane];
        }
#pragma unroll
        for (int q = 0; q < 8; q++) {
            acc.x += v[q].x; acc.y += v[q].y; acc.z += v[q].z; acc.w += v[q].w;
        }
    }
    for (; j < e; j++) {
        int s = g_eidx[j];
        float4 v = ((const float4*)(g_bufA + (size_t)s * F))[lane];
        acc.x += v.x; acc.y += v.y; acc.z += v.z; acc.w += v.w;
    }
    float db = g_dinvIn[node];
    float4 bb = ((const float4*)b2)[lane];
    float h[4];
    h[0] = fmaxf(fmaf(acc.x, db, bb.x), 0.f);
    h[1] = fmaxf(fmaf(acc.y, db, bb.y), 0.f);
    h[2] = fmaxf(fmaf(acc.z, db, bb.z), 0.f);
    h[3] = fmaxf(fmaf(acc.w, db, bb.w), 0.f);

    float a0 = 0.f, a1 = 0.f, a2 = 0.f, a3 = 0.f;
    const float4* Wc4 = (const float4*)Wc;
#pragma unroll
    for (int q = 0; q < 4; q++) {
        float4 w = Wc4[lane * 4 + q];
        a0 = fmaf(h[q], w.x, a0);
        a1 = fmaf(h[q], w.y, a1);
        a2 = fmaf(h[q], w.z, a2);
        a3 = fmaf(h[q], w.w, a3);
    }
#pragma unroll
    for (int o = 16; o > 0; o >>= 1) {
        a0 += __shfl_xor_sync(0xffffffffu, a0, o);
        a1 += __shfl_xor_sync(0xffffffffu, a1, o);
        a2 += __shfl_xor_sync(0xffffffffu, a2, o);
        a3 += __shfl_xor_sync(0xffffffffu, a3, o);
    }
    if (lane == 0)
        ((float4*)out)[node] = make_float4(a0 + bc[0], a1 + bc[1], a2 + bc[2], a3 + bc[3]);
}

// ---------------------------------------------------------------------------
extern "C" void kernel_launch(void* const* d_in, const int* in_sizes, int n_in,
                              void* d_out, int out_size) {
    const float* features = (const float*)d_in[0];
    const int*   src      = (const int*)d_in[1];
    const int*   dst      = (const int*)d_in[2];
    const float* W1       = (const float*)d_in[3];
    const float* b1       = (const float*)d_in[4];
    const float* W2       = (const float*)d_in[5];
    const float* b2       = (const float*)d_in[6];
    const float* Wc       = (const float*)d_in[7];
    const float* bc       = (const float*)d_in[8];
    float*       out      = (float*)d_out;

    const int nN  = in_sizes[0] / F;
    const int nE  = in_sizes[1];
    const int nb  = (nN + SCAN_B - 1) / SCAN_B;
    const int nE2 = nE >> 1;
    const int odd = nE & 1;
    const int nBlocks = (nN + 127) / 128;

    unsigned short *w1hi, *w1lo, *w2hi, *w2lo;
    cudaGetSymbolAddress((void**)&w1hi, g_W1hi);
    cudaGetSymbolAddress((void**)&w1lo, g_W1lo);
    cudaGetSymbolAddress((void**)&w2hi, g_W2hi);
    cudaGetSymbolAddress((void**)&w2lo, g_W2lo);

    static cudaStream_t s1 = nullptr;
    static cudaEvent_t  eH = nullptr, eD = nullptr, eG = nullptr;
    if (!s1) {
        cudaStreamCreateWithFlags(&s1, cudaStreamNonBlocking);
        cudaEventCreateWithFlags(&eH, cudaEventDisableTiming);
        cudaEventCreateWithFlags(&eD, cudaEventDisableTiming);
        cudaEventCreateWithFlags(&eG, cudaEventDisableTiming);
    }

    // stream0: fused setup (zero histograms + weight split), then hist
    {
        int setupN = (nN > 2 * F * F) ? nN : 2 * F * F;
        setup_kernel<<<(setupN + 255) / 256, 256>>>(W1, W2, nN);
    }
    hist_kernel<<<(nE2 + 256) / 256, 256>>>((const int2*)src, (const int2*)dst,
                                            nE2, odd, src, dst);
    cudaEventRecord(eH, 0);

    // s1: prep after hist — the eH wait is also the capture-join for s1,
    // so every s1 kernel is a graph node (re-runs on every replay).
    cudaStreamWaitEvent(s1, eH, 0);
    prep_kernel<<<(nN * 32 + 255) / 256, 256, 0, s1>>>(features, nN);

    // stream0: scan (with fused dinv) -> record eD -> rest of CSR chain
    scan_block_kernel<<<nb, SCAN_B>>>(nN);
    cudaEventRecord(eD, 0);
    scan_small_kernel<<<1, 128>>>(nb);
    offsets_kernel<<<(nN + 255) / 256, 256>>>(nN);
    fill_kernel<<<(nE2 + 256) / 256, 256>>>((const int2*)src, (const int2*)dst,
                                            nE2, odd, src, dst);

    // s1: gemm1 needs prep (program order) + dinv/scan_block (event)
    cudaStreamWaitEvent(s1, eD, 0);
    gemm_mma_kernel<<<nBlocks, 256, 0, s1>>>(w1hi, w1lo, nN, 1);
    cudaEventRecord(eG, s1);

    // join, then fully serial L2-resident phase: gather1 -> gemm2 -> gather2
    cudaStreamWaitEvent(0, eG, 0);
    gather1_kernel<<<(nN + 7) / 8, 256>>>(b1, nN);
    gemm_mma_kernel<<<nBlocks, 256>>>(w2hi, w2lo, nN, 0);
    gather2_cls_kernel<<<(nN + 7) / 8, 256>>>(b2, Wc, bc, out, nN);
}

// round 16
// speedup vs baseline: 1.3981x; 1.3981x over previous
#include <cuda_runtime.h>
#include <cuda_bf16.h>
#include <cstdint>

#define F 128
#define MAXN 100000
#define MAXNP 100096   // padded to multiple of 128 (GEMM tile)
#define MAXE 1600000
#define SCAN_B 1024
#define MAXBLK ((MAXN + SCAN_B - 1) / SCAN_B)   // 98

// Scratch (allocation-free: __device__ globals)
__device__ __align__(16) float    g_bufA[(size_t)MAXNP * F];       // gemm out (both layers)
__device__ __align__(16) uint32_t g_Xhi[(size_t)MAXNP * (F / 2)];  // bf16 pairs
__device__ __align__(16) uint32_t g_Xlo[(size_t)MAXNP * (F / 2)];
__device__ __align__(4) unsigned short g_W1hi[F * F];  // [n][k] transposed
__device__ __align__(4) unsigned short g_W1lo[F * F];
__device__ __align__(4) unsigned short g_W2hi[F * F];
__device__ __align__(4) unsigned short g_W2lo[F * F];
__device__ int   g_cntIn[MAXN];
__device__ int   g_cntOut[MAXN];
__device__ int   g_excl[MAXN];
__device__ int   g_bsum[MAXBLK];
__device__ int   g_off[MAXN];
__device__ int   g_cursor[MAXN];
__device__ int   g_eidx[MAXE];
__device__ float g_dinvOut[MAXNP];   // padded rows stay 0 (never written)
__device__ float g_dinvIn[MAXNP];

__device__ __forceinline__ void split_bf16(float v, unsigned short& h, unsigned short& l) {
    __nv_bfloat16 hb = __float2bfloat16(v);
    __nv_bfloat16 lb = __float2bfloat16(v - __bfloat162float(hb));
    h = __bfloat16_as_ushort(hb);
    l = __bfloat16_as_ushort(lb);
}

// ---------------------------------------------------------------------------
__global__ void zero_cnt_kernel(int n) {
    int i = blockIdx.x * blockDim.x + threadIdx.x;
    if (i < n) { g_cntIn[i] = 0; g_cntOut[i] = 0; }
}

__global__ void hist_kernel(const int2* __restrict__ src2,
                            const int2* __restrict__ dst2, int nE2, int odd,
                            const int* __restrict__ src,
                            const int* __restrict__ dst) {
    int i = blockIdx.x * blockDim.x + threadIdx.x;
    if (i < nE2) {
        int2 s = src2[i];
        int2 d = dst2[i];
        atomicAdd(&g_cntOut[s.x], 1);
        atomicAdd(&g_cntOut[s.y], 1);
        atomicAdd(&g_cntIn[d.x], 1);
        atomicAdd(&g_cntIn[d.y], 1);
    } else if (i == nE2 && odd) {
        atomicAdd(&g_cntOut[src[2 * nE2]], 1);
        atomicAdd(&g_cntIn[dst[2 * nE2]], 1);
    }
}

__global__ void dinv_kernel(int n) {
    int i = blockIdx.x * blockDim.x + threadIdx.x;
    if (i < n) {
        g_dinvIn[i]  = rsqrtf(fmaxf((float)g_cntIn[i],  1.f));
        g_dinvOut[i] = rsqrtf(fmaxf((float)g_cntOut[i], 1.f));
    }
}

// Shuffle-based block scan (2 barriers)
__global__ void scan_block_kernel(int n) {
    __shared__ int wsum[32];
    int tid = threadIdx.x, lane = tid & 31, w = tid >> 5;
    int i = blockIdx.x * SCAN_B + tid;
    int v = (i < n) ? g_cntIn[i] : 0;
    int x = v;
#pragma unroll
    for (int o = 1; o < 32; o <<= 1) {
        int t = __shfl_up_sync(0xffffffffu, x, o);
        if (lane >= o) x += t;
    }
    if (lane == 31) wsum[w] = x;
    __syncthreads();
    if (w == 0) {
        int s = wsum[lane];
#pragma unroll
        for (int o = 1; o < 32; o <<= 1) {
            int t = __shfl_up_sync(0xffffffffu, s, o);
            if (lane >= o) s += t;
        }
        wsum[lane] = s;
    }
    __syncthreads();
    int incl = x + ((w > 0) ? wsum[w - 1] : 0);
    if (i < n) g_excl[i] = incl - v;
    if (tid == SCAN_B - 1) g_bsum[blockIdx.x] = incl;
}

__global__ void scan_small_kernel(int nb) {
    __shared__ int wsum[4];
    int tid = threadIdx.x, lane = tid & 31, w = tid >> 5;
    int v = (tid < nb) ? g_bsum[tid] : 0;
    int x = v;
#pragma unroll
    for (int o = 1; o < 32; o <<= 1) {
        int t = __shfl_up_sync(0xffffffffu, x, o);
        if (lane >= o) x += t;
    }
    if (lane == 31) wsum[w] = x;
    __syncthreads();
    int base = 0;
#pragma unroll
    for (int q = 0; q < 4; q++) base += (q < w) ? wsum[q] : 0;
    if (tid < nb) g_bsum[tid] = base + x - v;
}

__global__ void offsets_kernel(int n) {
    int i = blockIdx.x * blockDim.x + threadIdx.x;
    if (i < n) {
        int o = g_excl[i] + g_bsum[i / SCAN_B];
        g_off[i] = o;
        g_cursor[i] = o;
    }
}

__global__ void fill_kernel(const int2* __restrict__ src2,
                            const int2* __restrict__ dst2, int nE2, int odd,
                            const int* __restrict__ src,
                            const int* __restrict__ dst) {
    int i = blockIdx.x * blockDim.x + threadIdx.x;
    if (i < nE2) {
        int2 s = src2[i];
        int2 d = dst2[i];
        int p0 = atomicAdd(&g_cursor[d.x], 1);
        g_eidx[p0] = s.x;
        int p1 = atomicAdd(&g_cursor[d.y], 1);
        g_eidx[p1] = s.y;
    } else if (i == nE2 && odd) {
        int p = atomicAdd(&g_cursor[dst[2 * nE2]], 1);
        g_eidx[p] = src[2 * nE2];
    }
}

// ---------------------------------------------------------------------------
__global__ void wsplit_kernel(const float* __restrict__ W1,
                              const float* __restrict__ W2) {
    int t = blockIdx.x * blockDim.x + threadIdx.x;   // 0..32767
    int which = t >> 14;
    int i = t & 16383;
    int k = i >> 7, n = i & 127;
    unsigned short h, l;
    if (which == 0) {
        split_bf16(W1[i], h, l);
        g_W1hi[n * F + k] = h; g_W1lo[n * F + k] = l;
    } else {
        split_bf16(W2[i], h, l);
        g_W2hi[n * F + k] = h; g_W2lo[n * F + k] = l;
    }
}

// features -> split bf16 hi/lo (no scaling; dinvOut applied in gemm1 epilogue)
__global__ void prep_kernel(const float* __restrict__ feat, int nN) {
    int i = blockIdx.x * blockDim.x + threadIdx.x;   // one float4 each
    if (i >= nN * 32) return;
    int row = i >> 5, c4 = i & 31;
    float4 v = ((const float4*)feat)[i];
    unsigned short h0, l0, h1, l1, h2, l2, h3, l3;
    split_bf16(v.x, h0, l0); split_bf16(v.y, h1, l1);
    split_bf16(v.z, h2, l2); split_bf16(v.w, h3, l3);
    size_t w = (size_t)row * 64 + c4 * 2;
    g_Xhi[w]     = (uint32_t)h0 | ((uint32_t)h1 << 16);
    g_Xhi[w + 1] = (uint32_t)h2 | ((uint32_t)h3 << 16);
    g_Xlo[w]     = (uint32_t)l0 | ((uint32_t)l1 << 16);
    g_Xlo[w + 1] = (uint32_t)l2 | ((uint32_t)l3 << 16);
}

// ---------------------------------------------------------------------------
// bf16x3 tensor-core GEMM with ldmatrix; optional row-scale (dinvOut) on store.
#define XPITCH 40

__device__ __forceinline__ void mma_bf16(float* d, const uint32_t* a,
                                         uint32_t b0, uint32_t b1) {
    asm volatile(
        "mma.sync.aligned.m16n8k16.row.col.f32.bf16.bf16.f32 "
        "{%0,%1,%2,%3}, {%4,%5,%6,%7}, {%8,%9}, {%0,%1,%2,%3};"
        : "+f"(d[0]), "+f"(d[1]), "+f"(d[2]), "+f"(d[3])
        : "r"(a[0]), "r"(a[1]), "r"(a[2]), "r"(a[3]), "r"(b0), "r"(b1));
}

__device__ __forceinline__ void ldsm_x4(uint32_t& r0, uint32_t& r1,
                                        uint32_t& r2, uint32_t& r3,
                                        const void* p) {
    uint32_t a = (uint32_t)__cvta_generic_to_shared(p);
    asm volatile("ldmatrix.sync.aligned.m8n8.x4.shared.b16 {%0,%1,%2,%3}, [%4];"
                 : "=r"(r0), "=r"(r1), "=r"(r2), "=r"(r3) : "r"(a));
}

__global__ __launch_bounds__(256, 2)
void gemm_mma_kernel(const unsigned short* __restrict__ Whi,
                     const unsigned short* __restrict__ Wlo, int nN,
                     int scaleOut) {
    __shared__ __align__(16) unsigned short sXhi[128][XPITCH];
    __shared__ __align__(16) unsigned short sXlo[128][XPITCH];
    __shared__ __align__(16) unsigned short sWhi[128][XPITCH];
    __shared__ __align__(16) unsigned short sWlo[128][XPITCH];

    const int tid  = threadIdx.x;
    const int wid  = tid >> 5;
    const int lane = tid & 31;
    const int g    = lane >> 2;
    const int tig  = lane & 3;
    const int row0 = blockIdx.x * 128;
    const int wm   = wid & 3;
    const int wn   = wid >> 2;
    const uint32_t* Wh32 = (const uint32_t*)Whi;
    const uint32_t* Wl32 = (const uint32_t*)Wlo;

    const int lrow = (lane & 7) + ((lane >> 3) & 1) * 8;
    const int lcol = (lane >> 4) * 8;

    float acc[2][8][4];
#pragma unroll
    for (int mt = 0; mt < 2; mt++)
#pragma unroll
        for (int nt = 0; nt < 8; nt++)
#pragma unroll
            for (int q = 0; q < 4; q++) acc[mt][nt][q] = 0.f;

    for (int kc = 0; kc < 4; kc++) {
#pragma unroll
        for (int p = 0; p < 8; p++) {
            int idx = p * 256 + tid;
            int r   = idx >> 4;
            int pp  = idx & 15;
            int grow = row0 + r;
            uint32_t hw = 0, lw = 0;
            if (grow < nN) {
                size_t widx = (size_t)grow * 64 + kc * 16 + pp;
                hw = g_Xhi[widx];
                lw = g_Xlo[widx];
            }
            *(uint32_t*)&sXhi[r][2 * pp] = hw;
            *(uint32_t*)&sXlo[r][2 * pp] = lw;
        }
#pragma unroll
        for (int p = 0; p < 8; p++) {
            int idx = p * 256 + tid;
            int n   = idx >> 4;
            int pp  = idx & 15;
            int widx = n * 64 + kc * 16 + pp;
            *(uint32_t*)&sWhi[n][2 * pp] = Wh32[widx];
            *(uint32_t*)&sWlo[n][2 * pp] = Wl32[widx];
        }
        __syncthreads();

#pragma unroll
        for (int ks = 0; ks < 2; ks++) {
            int kb = ks * 16;
            uint32_t ah[2][4], al[2][4];
#pragma unroll
            for (int mt = 0; mt < 2; mt++) {
                int rb = wm * 32 + mt * 16;
                ldsm_x4(ah[mt][0], ah[mt][1], ah[mt][2], ah[mt][3],
                        &sXhi[rb + lrow][kb + lcol]);
                ldsm_x4(al[mt][0], al[mt][1], al[mt][2], al[mt][3],
                        &sXlo[rb + lrow][kb + lcol]);
            }
#pragma unroll
            for (int ntp = 0; ntp < 4; ntp++) {
                int n0 = wn * 64 + ntp * 16;
                uint32_t bh[4], bl[4];
                ldsm_x4(bh[0], bh[1], bh[2], bh[3], &sWhi[n0 + lrow][kb + lcol]);
                ldsm_x4(bl[0], bl[1], bl[2], bl[3], &sWlo[n0 + lrow][kb + lcol]);
#pragma unroll
                for (int sub = 0; sub < 2; sub++) {
                    int nt = 2 * ntp + sub;
#pragma unroll
                    for (int mt = 0; mt < 2; mt++) {
                        mma_bf16(acc[mt][nt], ah[mt], bh[sub], bh[2 + sub]);
                        mma_bf16(acc[mt][nt], ah[mt], bl[sub], bl[2 + sub]);
                        mma_bf16(acc[mt][nt], al[mt], bh[sub], bh[2 + sub]);
                    }
                }
            }
        }
        __syncthreads();
    }

#pragma unroll
    for (int mt = 0; mt < 2; mt++) {
        int r1 = row0 + wm * 32 + mt * 16 + g;
        float sa = 1.f, sb = 1.f;
        if (scaleOut) {
            sa = g_dinvOut[r1];       // padded rows read deterministic 0
            sb = g_dinvOut[r1 + 8];
        }
#pragma unroll
        for (int nt = 0; nt < 8; nt++) {
            int col = wn * 64 + nt * 8 + 2 * tig;
            *(float2*)(g_bufA + (size_t)r1 * F + col) =
                make_float2(acc[mt][nt][0] * sa, acc[mt][nt][1] * sa);
            *(float2*)(g_bufA + (size_t)(r1 + 8) * F + col) =
                make_float2(acc[mt][nt][2] * sb, acc[mt][nt][3] * sb);
        }
    }
}

// ---------------------------------------------------------------------------
// Gather-1: aggregate over bufA (unroll 8) + layer-2 transform + split -> Xhi/Xlo
__global__ void gather1_kernel(const float* __restrict__ b1, int nN) {
    int node = blockIdx.x * (blockDim.x >> 5) + (threadIdx.x >> 5);
    int lane = threadIdx.x & 31;
    if (node >= nN) return;
    int b = g_off[node];
    int e = b + g_cntIn[node];
    float4 acc = make_float4(0.f, 0.f, 0.f, 0.f);
    int j = b;
    int e8 = b + ((e - b) & ~7);
    for (; j < e8; j += 8) {
        float4 v[8];
#pragma unroll
        for (int q = 0; q < 8; q++) {
            int s = g_eidx[j + q];
            v[q] = ((const float4*)(g_bufA + (size_t)s * F))[lane];
        }
#pragma unroll
        for (int q = 0; q < 8; q++) {
            acc.x += v[q].x; acc.y += v[q].y; acc.z += v[q].z; acc.w += v[q].w;
        }
    }
    for (; j < e; j++) {
        int s = g_eidx[j];
        float4 v = ((const float4*)(g_bufA + (size_t)s * F))[lane];
        acc.x += v.x; acc.y += v.y; acc.z += v.z; acc.w += v.w;
    }
    float db = g_dinvIn[node];
    float da = g_dinvOut[node];
    float4 bb = ((const float4*)b1)[lane];
    float x0 = fmaxf(fmaf(acc.x, db, bb.x), 0.f) * da;
    float x1 = fmaxf(fmaf(acc.y, db, bb.y), 0.f) * da;
    float x2 = fmaxf(fmaf(acc.z, db, bb.z), 0.f) * da;
    float x3 = fmaxf(fmaf(acc.w, db, bb.w), 0.f) * da;
    unsigned short h0, l0, h1, l1, h2, l2, h3, l3;
    split_bf16(x0, h0, l0); split_bf16(x1, h1, l1);
    split_bf16(x2, h2, l2); split_bf16(x3, h3, l3);
    size_t w = (size_t)node * 64 + lane * 2;
    g_Xhi[w]     = (uint32_t)h0 | ((uint32_t)h1 << 16);
    g_Xhi[w + 1] = (uint32_t)h2 | ((uint32_t)h3 << 16);
    g_Xlo[w]     = (uint32_t)l0 | ((uint32_t)l1 << 16);
    g_Xlo[w + 1] = (uint32_t)l2 | ((uint32_t)l3 << 16);
}

// ---------------------------------------------------------------------------
// Gather-2 over bufA (unroll 8) + fused classifier
__global__ void gather2_cls_kernel(const float* __restrict__ b2,
                                   const float* __restrict__ Wc,
                                   const float* __restrict__ bc,
                                   float* __restrict__ out, int nN) {
    int node = blockIdx.x * (blockDim.x >> 5) + (threadIdx.x >> 5);
    int lane = threadIdx.x & 31;
    if (node >= nN) return;
    int b = g_off[node];
    int e = b + g_cntIn[node];
    float4 acc = make_float4(0.f, 0.f, 0.f, 0.f);
    int j = b;
    int e8 = b + ((e - b) & ~7);
    for (; j < e8; j += 8) {
        float4 v[8];
#pragma unroll
        for (int q = 0; q < 8; q++) {
            int s = g_eidx[j + q];
            v[q] = ((const float4*)(g_bufA + (size_t)s * F))[lane];
        }
#pragma unroll
        for (int q = 0; q < 8; q++) {
            acc.x += v[q].x; acc.y += v[q].y; acc.z += v[q].z; acc.w += v[q].w;
        }
    }
    for (; j < e; j++) {
        int s = g_eidx[j];
        float4 v = ((const float4*)(g_bufA + (size_t)s * F))[lane];
        acc.x += v.x; acc.y += v.y; acc.z += v.z; acc.w += v.w;
    }
    float db = g_dinvIn[node];
    float4 bb = ((const float4*)b2)[lane];
    float h[4];
    h[0] = fmaxf(fmaf(acc.x, db, bb.x), 0.f);
    h[1] = fmaxf(fmaf(acc.y, db, bb.y), 0.f);
    h[2] = fmaxf(fmaf(acc.z, db, bb.z), 0.f);
    h[3] = fmaxf(fmaf(acc.w, db, bb.w), 0.f);

    float a0 = 0.f, a1 = 0.f, a2 = 0.f, a3 = 0.f;
    const float4* Wc4 = (const float4*)Wc;
#pragma unroll
    for (int q = 0; q < 4; q++) {
        float4 w = Wc4[lane * 4 + q];
        a0 = fmaf(h[q], w.x, a0);
        a1 = fmaf(h[q], w.y, a1);
        a2 = fmaf(h[q], w.z, a2);
        a3 = fmaf(h[q], w.w, a3);
    }
#pragma unroll
    for (int o = 16; o > 0; o >>= 1) {
        a0 += __shfl_xor_sync(0xffffffffu, a0, o);
        a1 += __shfl_xor_sync(0xffffffffu, a1, o);
        a2 += __shfl_xor_sync(0xffffffffu, a2, o);
        a3 += __shfl_xor_sync(0xffffffffu, a3, o);
    }
    if (lane == 0)
        ((float4*)out)[node] = make_float4(a0 + bc[0], a1 + bc[1], a2 + bc[2], a3 + bc[3]);
}

// ---------------------------------------------------------------------------
extern "C" void kernel_launch(void* const* d_in, const int* in_sizes, int n_in,
                              void* d_out, int out_size) {
    const float* features = (const float*)d_in[0];
    const int*   src      = (const int*)d_in[1];
    const int*   dst      = (const int*)d_in[2];
    const float* W1       = (const float*)d_in[3];
    const float* b1       = (const float*)d_in[4];
    const float* W2       = (const float*)d_in[5];
    const float* b2       = (const float*)d_in[6];
    const float* Wc       = (const float*)d_in[7];
    const float* bc       = (const float*)d_in[8];
    float*       out      = (float*)d_out;

    const int nN  = in_sizes[0] / F;
    const int nE  = in_sizes[1];
    const int nb  = (nN + SCAN_B - 1) / SCAN_B;
    const int nE2 = nE >> 1;
    const int odd = nE & 1;
    const int nBlocks = (nN + 127) / 128;

    unsigned short *w1hi, *w1lo, *w2hi, *w2lo;
    cudaGetSymbolAddress((void**)&w1hi, g_W1hi);
    cudaGetSymbolAddress((void**)&w1lo, g_W1lo);
    cudaGetSymbolAddress((void**)&w2hi, g_W2hi);
    cudaGetSymbolAddress((void**)&w2lo, g_W2lo);

    static cudaStream_t s1 = nullptr;
    static cudaEvent_t  eS = nullptr, eH = nullptr, eD = nullptr, eG = nullptr;
    if (!s1) {
        cudaStreamCreateWithFlags(&s1, cudaStreamNonBlocking);
        cudaEventCreateWithFlags(&eS, cudaEventDisableTiming);
        cudaEventCreateWithFlags(&eH, cudaEventDisableTiming);
        cudaEventCreateWithFlags(&eD, cudaEventDisableTiming);
        cudaEventCreateWithFlags(&eG, cudaEventDisableTiming);
    }

    // FORK: s1 joins capture via an event from the capturing stream BEFORE any
    // s1 work, so all s1 kernels are graph nodes (re-run on every replay).
    cudaEventRecord(eS, 0);
    cudaStreamWaitEvent(s1, eS, 0);

    // s1: weight split only (tiny; off critical path)
    wsplit_kernel<<<128, 256, 0, s1>>>(W1, W2);

    // stream0: degrees (hist runs without streaming contention)
    zero_cnt_kernel<<<(nN + 255) / 256, 256>>>(nN);
    hist_kernel<<<(nE2 + 256) / 256, 256>>>((const int2*)src, (const int2*)dst,
                                            nE2, odd, src, dst);
    cudaEventRecord(eH, 0);
    dinv_kernel<<<(nN + 255) / 256, 256>>>(nN);
    cudaEventRecord(eD, 0);

    // s1: prep after hist (proven placement; overlaps dinv + scan chain)
    cudaStreamWaitEvent(s1, eH, 0);
    prep_kernel<<<(nN * 32 + 255) / 256, 256, 0, s1>>>(features, nN);
    // gemm1 needs prep+wsplit (program order) + dinv (event)
    cudaStreamWaitEvent(s1, eD, 0);
    gemm_mma_kernel<<<nBlocks, 256, 0, s1>>>(w1hi, w1lo, nN, 1);
    cudaEventRecord(eG, s1);

    // stream0: CSR offsets + fill (overlaps prep/gemm1)
    scan_block_kernel<<<nb, SCAN_B>>>(nN);
    scan_small_kernel<<<1, 128>>>(nb);
    offsets_kernel<<<(nN + 255) / 256, 256>>>(nN);
    fill_kernel<<<(nE2 + 256) / 256, 256>>>((const int2*)src, (const int2*)dst,
                                            nE2, odd, src, dst);

    // join, then fully serial L2-resident phase: gather1 -> gemm2 -> gather2
    cudaStreamWaitEvent(0, eG, 0);
    gather1_kernel<<<(nN + 7) / 8, 256>>>(b1, nN);
    gemm_mma_kernel<<<nBlocks, 256>>>(w2hi, w2lo, nN, 0);
    gather2_cls_kernel<<<(nN + 7) / 8, 256>>>(b2, Wc, bc, out, nN);
}

// round 17
// speedup vs baseline: 1.5054x; 1.0767x over previous
#include <cuda_runtime.h>
#include <cuda_bf16.h>
#include <cuda_fp16.h>
#include <cstdint>

#define F 128
#define MAXN 100000
#define MAXNP 100096   // padded to multiple of 128 (GEMM tile)
#define MAXE 1600000
#define SCAN_B 1024
#define MAXBLK ((MAXN + SCAN_B - 1) / SCAN_B)   // 98

// Scratch (allocation-free: __device__ globals)
__device__ __align__(16) uint32_t g_bufA16[(size_t)MAXNP * (F / 2)]; // fp16 pairs, 25.6 MB
__device__ __align__(16) uint32_t g_Xhi[(size_t)MAXNP * (F / 2)];    // bf16 pairs
__device__ __align__(16) uint32_t g_Xlo[(size_t)MAXNP * (F / 2)];
__device__ __align__(4) unsigned short g_W1hi[F * F];  // [n][k] transposed
__device__ __align__(4) unsigned short g_W1lo[F * F];
__device__ __align__(4) unsigned short g_W2hi[F * F];
__device__ __align__(4) unsigned short g_W2lo[F * F];
__device__ int   g_cntIn[MAXN];
__device__ int   g_cntOut[MAXN];
__device__ int   g_excl[MAXN];
__device__ int   g_bsum[MAXBLK];
__device__ int   g_off[MAXN];
__device__ int   g_cursor[MAXN];
__device__ int   g_eidx[MAXE];
__device__ float g_dinvOut[MAXNP];   // padded rows stay 0 (never written)
__device__ float g_dinvIn[MAXNP];

__device__ __forceinline__ void split_bf16(float v, unsigned short& h, unsigned short& l) {
    __nv_bfloat16 hb = __float2bfloat16(v);
    __nv_bfloat16 lb = __float2bfloat16(v - __bfloat162float(hb));
    h = __bfloat16_as_ushort(hb);
    l = __bfloat16_as_ushort(lb);
}

// ---------------------------------------------------------------------------
__global__ void zero_cnt_kernel(int n) {
    int i = blockIdx.x * blockDim.x + threadIdx.x;
    if (i < n) { g_cntIn[i] = 0; g_cntOut[i] = 0; }
}

__global__ void hist_kernel(const int2* __restrict__ src2,
                            const int2* __restrict__ dst2, int nE2, int odd,
                            const int* __restrict__ src,
                            const int* __restrict__ dst) {
    int i = blockIdx.x * blockDim.x + threadIdx.x;
    if (i < nE2) {
        int2 s = src2[i];
        int2 d = dst2[i];
        atomicAdd(&g_cntOut[s.x], 1);
        atomicAdd(&g_cntOut[s.y], 1);
        atomicAdd(&g_cntIn[d.x], 1);
        atomicAdd(&g_cntIn[d.y], 1);
    } else if (i == nE2 && odd) {
        atomicAdd(&g_cntOut[src[2 * nE2]], 1);
        atomicAdd(&g_cntIn[dst[2 * nE2]], 1);
    }
}

__global__ void dinv_kernel(int n) {
    int i = blockIdx.x * blockDim.x + threadIdx.x;
    if (i < n) {
        g_dinvIn[i]  = rsqrtf(fmaxf((float)g_cntIn[i],  1.f));
        g_dinvOut[i] = rsqrtf(fmaxf((float)g_cntOut[i], 1.f));
    }
}

// Shuffle-based block scan (2 barriers)
__global__ void scan_block_kernel(int n) {
    __shared__ int wsum[32];
    int tid = threadIdx.x, lane = tid & 31, w = tid >> 5;
    int i = blockIdx.x * SCAN_B + tid;
    int v = (i < n) ? g_cntIn[i] : 0;
    int x = v;
#pragma unroll
    for (int o = 1; o < 32; o <<= 1) {
        int t = __shfl_up_sync(0xffffffffu, x, o);
        if (lane >= o) x += t;
    }
    if (lane == 31) wsum[w] = x;
    __syncthreads();
    if (w == 0) {
        int s = wsum[lane];
#pragma unroll
        for (int o = 1; o < 32; o <<= 1) {
            int t = __shfl_up_sync(0xffffffffu, s, o);
            if (lane >= o) s += t;
        }
        wsum[lane] = s;
    }
    __syncthreads();
    int incl = x + ((w > 0) ? wsum[w - 1] : 0);
    if (i < n) g_excl[i] = incl - v;
    if (tid == SCAN_B - 1) g_bsum[blockIdx.x] = incl;
}

__global__ void scan_small_kernel(int nb) {
    __shared__ int wsum[4];
    int tid = threadIdx.x, lane = tid & 31, w = tid >> 5;
    int v = (tid < nb) ? g_bsum[tid] : 0;
    int x = v;
#pragma unroll
    for (int o = 1; o < 32; o <<= 1) {
        int t = __shfl_up_sync(0xffffffffu, x, o);
        if (lane >= o) x += t;
    }
    if (lane == 31) wsum[w] = x;
    __syncthreads();
    int base = 0;
#pragma unroll
    for (int q = 0; q < 4; q++) base += (q < w) ? wsum[q] : 0;
    if (tid < nb) g_bsum[tid] = base + x - v;
}

__global__ void offsets_kernel(int n) {
    int i = blockIdx.x * blockDim.x + threadIdx.x;
    if (i < n) {
        int o = g_excl[i] + g_bsum[i / SCAN_B];
        g_off[i] = o;
        g_cursor[i] = o;
    }
}

__global__ void fill_kernel(const int2* __restrict__ src2,
                            const int2* __restrict__ dst2, int nE2, int odd,
                            const int* __restrict__ src,
                            const int* __restrict__ dst) {
    int i = blockIdx.x * blockDim.x + threadIdx.x;
    if (i < nE2) {
        int2 s = src2[i];
        int2 d = dst2[i];
        int p0 = atomicAdd(&g_cursor[d.x], 1);
        g_eidx[p0] = s.x;
        int p1 = atomicAdd(&g_cursor[d.y], 1);
        g_eidx[p1] = s.y;
    } else if (i == nE2 && odd) {
        int p = atomicAdd(&g_cursor[dst[2 * nE2]], 1);
        g_eidx[p] = src[2 * nE2];
    }
}

// ---------------------------------------------------------------------------
__global__ void wsplit_kernel(const float* __restrict__ W1,
                              const float* __restrict__ W2) {
    int t = blockIdx.x * blockDim.x + threadIdx.x;   // 0..32767
    int which = t >> 14;
    int i = t & 16383;
    int k = i >> 7, n = i & 127;
    unsigned short h, l;
    if (which == 0) {
        split_bf16(W1[i], h, l);
        g_W1hi[n * F + k] = h; g_W1lo[n * F + k] = l;
    } else {
        split_bf16(W2[i], h, l);
        g_W2hi[n * F + k] = h; g_W2lo[n * F + k] = l;
    }
}

// features -> split bf16 hi/lo (no scaling; dinvOut applied in gemm1 epilogue)
__global__ void prep_kernel(const float* __restrict__ feat, int nN) {
    int i = blockIdx.x * blockDim.x + threadIdx.x;   // one float4 each
    if (i >= nN * 32) return;
    int row = i >> 5, c4 = i & 31;
    float4 v = ((const float4*)feat)[i];
    unsigned short h0, l0, h1, l1, h2, l2, h3, l3;
    split_bf16(v.x, h0, l0); split_bf16(v.y, h1, l1);
    split_bf16(v.z, h2, l2); split_bf16(v.w, h3, l3);
    size_t w = (size_t)row * 64 + c4 * 2;
    g_Xhi[w]     = (uint32_t)h0 | ((uint32_t)h1 << 16);
    g_Xhi[w + 1] = (uint32_t)h2 | ((uint32_t)h3 << 16);
    g_Xlo[w]     = (uint32_t)l0 | ((uint32_t)l1 << 16);
    g_Xlo[w + 1] = (uint32_t)l2 | ((uint32_t)l3 << 16);
}

// ---------------------------------------------------------------------------
// bf16x3 tensor-core GEMM with ldmatrix; fp16 output; optional row-scale.
#define XPITCH 40

__device__ __forceinline__ void mma_bf16(float* d, const uint32_t* a,
                                         uint32_t b0, uint32_t b1) {
    asm volatile(
        "mma.sync.aligned.m16n8k16.row.col.f32.bf16.bf16.f32 "
        "{%0,%1,%2,%3}, {%4,%5,%6,%7}, {%8,%9}, {%0,%1,%2,%3};"
        : "+f"(d[0]), "+f"(d[1]), "+f"(d[2]), "+f"(d[3])
        : "r"(a[0]), "r"(a[1]), "r"(a[2]), "r"(a[3]), "r"(b0), "r"(b1));
}

__device__ __forceinline__ void ldsm_x4(uint32_t& r0, uint32_t& r1,
                                        uint32_t& r2, uint32_t& r3,
                                        const void* p) {
    uint32_t a = (uint32_t)__cvta_generic_to_shared(p);
    asm volatile("ldmatrix.sync.aligned.m8n8.x4.shared.b16 {%0,%1,%2,%3}, [%4];"
                 : "=r"(r0), "=r"(r1), "=r"(r2), "=r"(r3) : "r"(a));
}

__global__ __launch_bounds__(256, 2)
void gemm_mma_kernel(const unsigned short* __restrict__ Whi,
                     const unsigned short* __restrict__ Wlo, int nN,
                     int scaleOut) {
    __shared__ __align__(16) unsigned short sXhi[128][XPITCH];
    __shared__ __align__(16) unsigned short sXlo[128][XPITCH];
    __shared__ __align__(16) unsigned short sWhi[128][XPITCH];
    __shared__ __align__(16) unsigned short sWlo[128][XPITCH];

    const int tid  = threadIdx.x;
    const int wid  = tid >> 5;
    const int lane = tid & 31;
    const int g    = lane >> 2;
    const int tig  = lane & 3;
    const int row0 = blockIdx.x * 128;
    const int wm   = wid & 3;
    const int wn   = wid >> 2;
    const uint32_t* Wh32 = (const uint32_t*)Whi;
    const uint32_t* Wl32 = (const uint32_t*)Wlo;

    const int lrow = (lane & 7) + ((lane >> 3) & 1) * 8;
    const int lcol = (lane >> 4) * 8;

    float acc[2][8][4];
#pragma unroll
    for (int mt = 0; mt < 2; mt++)
#pragma unroll
        for (int nt = 0; nt < 8; nt++)
#pragma unroll
            for (int q = 0; q < 4; q++) acc[mt][nt][q] = 0.f;

    for (int kc = 0; kc < 4; kc++) {
#pragma unroll
        for (int p = 0; p < 8; p++) {
            int idx = p * 256 + tid;
            int r   = idx >> 4;
            int pp  = idx & 15;
            int grow = row0 + r;
            uint32_t hw = 0, lw = 0;
            if (grow < nN) {
                size_t widx = (size_t)grow * 64 + kc * 16 + pp;
                hw = g_Xhi[widx];
                lw = g_Xlo[widx];
            }
            *(uint32_t*)&sXhi[r][2 * pp] = hw;
            *(uint32_t*)&sXlo[r][2 * pp] = lw;
        }
#pragma unroll
        for (int p = 0; p < 8; p++) {
            int idx = p * 256 + tid;
            int n   = idx >> 4;
            int pp  = idx & 15;
            int widx = n * 64 + kc * 16 + pp;
            *(uint32_t*)&sWhi[n][2 * pp] = Wh32[widx];
            *(uint32_t*)&sWlo[n][2 * pp] = Wl32[widx];
        }
        __syncthreads();

#pragma unroll
        for (int ks = 0; ks < 2; ks++) {
            int kb = ks * 16;
            uint32_t ah[2][4], al[2][4];
#pragma unroll
            for (int mt = 0; mt < 2; mt++) {
                int rb = wm * 32 + mt * 16;
                ldsm_x4(ah[mt][0], ah[mt][1], ah[mt][2], ah[mt][3],
                        &sXhi[rb + lrow][kb + lcol]);
                ldsm_x4(al[mt][0], al[mt][1], al[mt][2], al[mt][3],
                        &sXlo[rb + lrow][kb + lcol]);
            }
#pragma unroll
            for (int ntp = 0; ntp < 4; ntp++) {
                int n0 = wn * 64 + ntp * 16;
                uint32_t bh[4], bl[4];
                ldsm_x4(bh[0], bh[1], bh[2], bh[3], &sWhi[n0 + lrow][kb + lcol]);
                ldsm_x4(bl[0], bl[1], bl[2], bl[3], &sWlo[n0 + lrow][kb + lcol]);
#pragma unroll
                for (int sub = 0; sub < 2; sub++) {
                    int nt = 2 * ntp + sub;
#pragma unroll
                    for (int mt = 0; mt < 2; mt++) {
                        mma_bf16(acc[mt][nt], ah[mt], bh[sub], bh[2 + sub]);
                        mma_bf16(acc[mt][nt], ah[mt], bl[sub], bl[2 + sub]);
                        mma_bf16(acc[mt][nt], al[mt], bh[sub], bh[2 + sub]);
                    }
                }
            }
        }
        __syncthreads();
    }

    // fp16 store: halves gather traffic downstream
#pragma unroll
    for (int mt = 0; mt < 2; mt++) {
        int r1 = row0 + wm * 32 + mt * 16 + g;
        float sa = 1.f, sb = 1.f;
        if (scaleOut) {
            sa = g_dinvOut[r1];       // padded rows read deterministic 0
            sb = g_dinvOut[r1 + 8];
        }
#pragma unroll
        for (int nt = 0; nt < 8; nt++) {
            int ci = (wn * 64 + nt * 8 + 2 * tig) >> 1;  // half2 index in row
            __half2 ha = __floats2half2_rn(acc[mt][nt][0] * sa, acc[mt][nt][1] * sa);
            __half2 hb = __floats2half2_rn(acc[mt][nt][2] * sb, acc[mt][nt][3] * sb);
            g_bufA16[(size_t)r1 * 64 + ci]       = *(uint32_t*)&ha;
            g_bufA16[(size_t)(r1 + 8) * 64 + ci] = *(uint32_t*)&hb;
        }
    }
}

// ---------------------------------------------------------------------------
__device__ __forceinline__ void acc_half4(float4& acc, uint2 w) {
    float2 a = __half22float2(*(__half2*)&w.x);
    float2 b = __half22float2(*(__half2*)&w.y);
    acc.x += a.x; acc.y += a.y; acc.z += b.x; acc.w += b.y;
}

// Gather-1: aggregate fp16 rows (unroll 8) + layer-2 transform + split -> Xhi/Xlo
__global__ void gather1_kernel(const float* __restrict__ b1, int nN) {
    int node = blockIdx.x * (blockDim.x >> 5) + (threadIdx.x >> 5);
    int lane = threadIdx.x & 31;
    if (node >= nN) return;
    int b = g_off[node];
    int e = b + g_cntIn[node];
    float4 acc = make_float4(0.f, 0.f, 0.f, 0.f);
    int j = b;
    int e8 = b + ((e - b) & ~7);
    for (; j < e8; j += 8) {
        uint2 v[8];
#pragma unroll
        for (int q = 0; q < 8; q++) {
            int s = g_eidx[j + q];
            v[q] = ((const uint2*)(g_bufA16 + (size_t)s * 64))[lane];
        }
#pragma unroll
        for (int q = 0; q < 8; q++) acc_half4(acc, v[q]);
    }
    for (; j < e; j++) {
        int s = g_eidx[j];
        uint2 v = ((const uint2*)(g_bufA16 + (size_t)s * 64))[lane];
        acc_half4(acc, v);
    }
    float db = g_dinvIn[node];
    float da = g_dinvOut[node];
    float4 bb = ((const float4*)b1)[lane];
    float x0 = fmaxf(fmaf(acc.x, db, bb.x), 0.f) * da;
    float x1 = fmaxf(fmaf(acc.y, db, bb.y), 0.f) * da;
    float x2 = fmaxf(fmaf(acc.z, db, bb.z), 0.f) * da;
    float x3 = fmaxf(fmaf(acc.w, db, bb.w), 0.f) * da;
    unsigned short h0, l0, h1, l1, h2, l2, h3, l3;
    split_bf16(x0, h0, l0); split_bf16(x1, h1, l1);
    split_bf16(x2, h2, l2); split_bf16(x3, h3, l3);
    size_t w = (size_t)node * 64 + lane * 2;
    g_Xhi[w]     = (uint32_t)h0 | ((uint32_t)h1 << 16);
    g_Xhi[w + 1] = (uint32_t)h2 | ((uint32_t)h3 << 16);
    g_Xlo[w]     = (uint32_t)l0 | ((uint32_t)l1 << 16);
    g_Xlo[w + 1] = (uint32_t)l2 | ((uint32_t)l3 << 16);
}

// ---------------------------------------------------------------------------
// Gather-2 over fp16 rows (unroll 8) + fused classifier
__global__ void gather2_cls_kernel(const float* __restrict__ b2,
                                   const float* __restrict__ Wc,
                                   const float* __restrict__ bc,
                                   float* __restrict__ out, int nN) {
    int node = blockIdx.x * (blockDim.x >> 5) + (threadIdx.x >> 5);
    int lane = threadIdx.x & 31;
    if (node >= nN) return;
    int b = g_off[node];
    int e = b + g_cntIn[node];
    float4 acc = make_float4(0.f, 0.f, 0.f, 0.f);
    int j = b;
    int e8 = b + ((e - b) & ~7);
    for (; j < e8; j += 8) {
        uint2 v[8];
#pragma unroll
        for (int q = 0; q < 8; q++) {
            int s = g_eidx[j + q];
            v[q] = ((const uint2*)(g_bufA16 + (size_t)s * 64))[lane];
        }
#pragma unroll
        for (int q = 0; q < 8; q++) acc_half4(acc, v[q]);
    }
    for (; j < e; j++) {
        int s = g_eidx[j];
        uint2 v = ((const uint2*)(g_bufA16 + (size_t)s * 64))[lane];
        acc_half4(acc, v);
    }
    float db = g_dinvIn[node];
    float4 bb = ((const float4*)b2)[lane];
    float h[4];
    h[0] = fmaxf(fmaf(acc.x, db, bb.x), 0.f);
    h[1] = fmaxf(fmaf(acc.y, db, bb.y), 0.f);
    h[2] = fmaxf(fmaf(acc.z, db, bb.z), 0.f);
    h[3] = fmaxf(fmaf(acc.w, db, bb.w), 0.f);

    float a0 = 0.f, a1 = 0.f, a2 = 0.f, a3 = 0.f;
    const float4* Wc4 = (const float4*)Wc;
#pragma unroll
    for (int q = 0; q < 4; q++) {
        float4 w = Wc4[lane * 4 + q];
        a0 = fmaf(h[q], w.x, a0);
        a1 = fmaf(h[q], w.y, a1);
        a2 = fmaf(h[q], w.z, a2);
        a3 = fmaf(h[q], w.w, a3);
    }
#pragma unroll
    for (int o = 16; o > 0; o >>= 1) {
        a0 += __shfl_xor_sync(0xffffffffu, a0, o);
        a1 += __shfl_xor_sync(0xffffffffu, a1, o);
        a2 += __shfl_xor_sync(0xffffffffu, a2, o);
        a3 += __shfl_xor_sync(0xffffffffu, a3, o);
    }
    if (lane == 0)
        ((float4*)out)[node] = make_float4(a0 + bc[0], a1 + bc[1], a2 + bc[2], a3 + bc[3]);
}

// ---------------------------------------------------------------------------
extern "C" void kernel_launch(void* const* d_in, const int* in_sizes, int n_in,
                              void* d_out, int out_size) {
    const float* features = (const float*)d_in[0];
    const int*   src      = (const int*)d_in[1];
    const int*   dst      = (const int*)d_in[2];
    const float* W1       = (const float*)d_in[3];
    const float* b1       = (const float*)d_in[4];
    const float* W2       = (const float*)d_in[5];
    const float* b2       = (const float*)d_in[6];
    const float* Wc       = (const float*)d_in[7];
    const float* bc       = (const float*)d_in[8];
    float*       out      = (float*)d_out;

    const int nN  = in_sizes[0] / F;
    const int nE  = in_sizes[1];
    const int nb  = (nN + SCAN_B - 1) / SCAN_B;
    const int nE2 = nE >> 1;
    const int odd = nE & 1;
    const int nBlocks = (nN + 127) / 128;

    unsigned short *w1hi, *w1lo, *w2hi, *w2lo;
    cudaGetSymbolAddress((void**)&w1hi, g_W1hi);
    cudaGetSymbolAddress((void**)&w1lo, g_W1lo);
    cudaGetSymbolAddress((void**)&w2hi, g_W2hi);
    cudaGetSymbolAddress((void**)&w2lo, g_W2lo);

    static cudaStream_t s1 = nullptr;
    static cudaEvent_t  eS = nullptr, eH = nullptr, eD = nullptr, eG = nullptr;
    if (!s1) {
        cudaStreamCreateWithFlags(&s1, cudaStreamNonBlocking);
        cudaEventCreateWithFlags(&eS, cudaEventDisableTiming);
        cudaEventCreateWithFlags(&eH, cudaEventDisableTiming);
        cudaEventCreateWithFlags(&eD, cudaEventDisableTiming);
        cudaEventCreateWithFlags(&eG, cudaEventDisableTiming);
    }

    // FORK: s1 joins capture via an event from the capturing stream BEFORE any
    // s1 work, so all s1 kernels are graph nodes (re-run on every replay).
    cudaEventRecord(eS, 0);
    cudaStreamWaitEvent(s1, eS, 0);

    // s1: weight split only (tiny; off critical path)
    wsplit_kernel<<<128, 256, 0, s1>>>(W1, W2);

    // stream0: degrees (hist runs without streaming contention)
    zero_cnt_kernel<<<(nN + 255) / 256, 256>>>(nN);
    hist_kernel<<<(nE2 + 256) / 256, 256>>>((const int2*)src, (const int2*)dst,
                                            nE2, odd, src, dst);
    cudaEventRecord(eH, 0);
    dinv_kernel<<<(nN + 255) / 256, 256>>>(nN);
    cudaEventRecord(eD, 0);

    // s1: prep after hist (proven placement; overlaps dinv + scan chain)
    cudaStreamWaitEvent(s1, eH, 0);
    prep_kernel<<<(nN * 32 + 255) / 256, 256, 0, s1>>>(features, nN);
    // gemm1 needs prep+wsplit (program order) + dinv (event)
    cudaStreamWaitEvent(s1, eD, 0);
    gemm_mma_kernel<<<nBlocks, 256, 0, s1>>>(w1hi, w1lo, nN, 1);
    cudaEventRecord(eG, s1);

    // stream0: CSR offsets + fill (overlaps prep/gemm1)
    scan_block_kernel<<<nb, SCAN_B>>>(nN);
    scan_small_kernel<<<1, 128>>>(nb);
    offsets_kernel<<<(nN + 255) / 256, 256>>>(nN);
    fill_kernel<<<(nE2 + 256) / 256, 256>>>((const int2*)src, (const int2*)dst,
                                            nE2, odd, src, dst);

    // join, then fully serial L2-resident phase: gather1 -> gemm2 -> gather2
    cudaStreamWaitEvent(0, eG, 0);
    gather1_kernel<<<(nN + 7) / 8, 256>>>(b1, nN);
    gemm_mma_kernel<<<nBlocks, 256>>>(w2hi, w2lo, nN, 0);
    gather2_cls_kernel<<<(nN + 7) / 8, 256>>>(b2, Wc, bc, out, nN);
}